// round 11
// baseline (speedup 1.0000x reference)
#include <cuda_runtime.h>
#include <cuda_fp16.h>
#include <math.h>
#include <stdint.h>

// Problem constants
#define NTOK 8192
#define DIM  2048
#define FDIM 5632
#define NE   8
#define NASSIGN (NTOK * 2)

// ---------------------------------------------------------------------------
// Scratch (device globals; no dynamic allocation allowed)
// ---------------------------------------------------------------------------
__device__ int   g_cnt[NE];
__device__ int   g_off[NE];
__device__ int   g_tok_eid[NASSIGN];
__device__ float g_tok_w[NASSIGN];
__device__ int   g_assign_slot[NASSIGN];
__device__ int   g_slot_token[NASSIGN];
__device__ float g_probsum[NE];
__device__ float g_fraccnt[NE];

__device__ __half g_xh [(size_t)NTOK * DIM];        //  34 MB: fp16 x
__device__ __half g_gwh[(size_t)NE * FDIM * DIM];   // 185 MB: fp16 gate_w
__device__ __half g_uwh[(size_t)NE * FDIM * DIM];   // 185 MB: fp16 up_w
__device__ __half g_dwh[(size_t)NE * DIM * FDIM];   // 185 MB: fp16 down_w
__device__ __half g_hh [(size_t)NASSIGN * FDIM];    // 185 MB: fp16 h
__device__ float  g_tmp[(size_t)NASSIGN * DIM];     // 134 MB: per-slot down out

// ---------------------------------------------------------------------------
// Helpers
// ---------------------------------------------------------------------------
__device__ __forceinline__ void mma_f16(float c[4], const uint32_t a[4],
                                        uint32_t b0, uint32_t b1) {
    asm volatile(
        "mma.sync.aligned.m16n8k16.row.col.f32.f16.f16.f32 "
        "{%0,%1,%2,%3}, {%4,%5,%6,%7}, {%8,%9}, {%0,%1,%2,%3};"
        : "+f"(c[0]), "+f"(c[1]), "+f"(c[2]), "+f"(c[3])
        : "r"(a[0]), "r"(a[1]), "r"(a[2]), "r"(a[3]), "r"(b0), "r"(b1));
}

#define LDSM_X4(r0, r1, r2, r3, addr) \
    asm volatile("ldmatrix.sync.aligned.m8n8.x4.shared.b16 {%0,%1,%2,%3}, [%4];" \
                 : "=r"(r0), "=r"(r1), "=r"(r2), "=r"(r3) : "r"(addr))

__device__ __forceinline__ float silu(float g) {
    return g / (1.f + __expf(-g));
}

__device__ __forceinline__ uint32_t smem_u32(const void* p) {
    uint32_t a;
    asm("{ .reg .u64 t; cvta.to.shared.u64 t, %1; cvt.u32.u64 %0, t; }"
        : "=r"(a) : "l"(p));
    return a;
}

#define CP_ASYNC16(sa, gp) \
    asm volatile("cp.async.cg.shared.global [%0], [%1], 16;" :: "r"(sa), "l"(gp))
#define CP_COMMIT() asm volatile("cp.async.commit_group;" ::: "memory")
#define CP_WAIT1()  asm volatile("cp.async.wait_group 1;" ::: "memory")

// Smem: K-slab = 64 halves (128B) per row + 16B pad -> 144B row stride.
// 2 stages: A at s*STAGE_B2, B at 2*STAGE_B2 + s*STAGE_B2.
#define ROWB      144
#define STAGE_B2  (128 * ROWB)                // 18432 bytes
#define B_BASE_B2 (2 * STAGE_B2)              // 36864
#define SMEM_BYTES (4 * STAGE_B2)             // 73728 bytes -> 3 CTAs/SM

// ---------------------------------------------------------------------------
// K1: merged weight cvt (gate, up, down) + counter reset
// ---------------------------------------------------------------------------
#define WN4 ((NE * FDIM * DIM) / 4)

__global__ void __launch_bounds__(256) cvtall_kernel(const float* __restrict__ gw,
                                                     const float* __restrict__ uw,
                                                     const float* __restrict__ dw) {
    if (blockIdx.x == 0 && threadIdx.x < NE) {
        g_cnt[threadIdx.x] = 0;
        g_probsum[threadIdx.x] = 0.f;
        g_fraccnt[threadIdx.x] = 0.f;
    }
    __half* gwh = g_gwh; __half* uwh = g_uwh; __half* dwh = g_dwh;
    int64_t i = (int64_t)blockIdx.x * blockDim.x + threadIdx.x;
    int64_t stride = (int64_t)gridDim.x * blockDim.x;
    const int64_t total = 3LL * WN4;
    for (; i < total; i += stride) {
        const float* src;
        __half* dst;
        int64_t j = i;
        if (j < WN4)            { src = gw; dst = gwh; }
        else if (j < 2LL * WN4) { src = uw; dst = uwh; j -= WN4; }
        else                    { src = dw; dst = dwh; j -= 2LL * WN4; }
        float4 v = ((const float4*)src)[j];
        __half2 h0 = __floats2half2_rn(v.x, v.y);
        __half2 h1 = __floats2half2_rn(v.z, v.w);
        uint2 u;
        u.x = *(const uint32_t*)&h0;
        u.y = *(const uint32_t*)&h1;
        ((uint2*)dst)[j] = u;
    }
}

// ---------------------------------------------------------------------------
// K2: router — 1 warp/token (fp32, exact); also emits fp16 x row.
// ---------------------------------------------------------------------------
__global__ void __launch_bounds__(256) router_kernel(const float* __restrict__ x,
                                                     const float* __restrict__ rw) {
    __shared__ float s_prob[NE], s_frac[NE];
    int tid = threadIdx.x;
    if (tid < NE) { s_prob[tid] = 0.f; s_frac[tid] = 0.f; }
    __syncthreads();

    int lane = tid & 31;
    int tok  = blockIdx.x * 8 + (tid >> 5);

    float acc[NE];
#pragma unroll
    for (int e = 0; e < NE; e++) acc[e] = 0.f;

    const float* xr = x + (size_t)tok * DIM;
    __half* xh = g_xh + (size_t)tok * DIM;
    for (int d = lane; d < DIM; d += 32) {
        float xv = xr[d];
        xh[d] = __float2half_rn(xv);
#pragma unroll
        for (int e = 0; e < NE; e++) acc[e] += xv * rw[e * DIM + d];
    }
#pragma unroll
    for (int e = 0; e < NE; e++) {
#pragma unroll
        for (int o = 16; o > 0; o >>= 1)
            acc[e] += __shfl_xor_sync(0xffffffffu, acc[e], o);
    }

    if (lane == 0) {
        float mx = acc[0];
#pragma unroll
        for (int e = 1; e < NE; e++) mx = fmaxf(mx, acc[e]);
        float p[NE]; float s = 0.f;
#pragma unroll
        for (int e = 0; e < NE; e++) { p[e] = expf(acc[e] - mx); s += p[e]; }
        float inv = 1.f / s;
#pragma unroll
        for (int e = 0; e < NE; e++) p[e] *= inv;

        int e1 = 0;
#pragma unroll
        for (int e = 1; e < NE; e++) if (p[e] > p[e1]) e1 = e;
        int e2 = (e1 == 0) ? 1 : 0;
#pragma unroll
        for (int e = 0; e < NE; e++) if (e != e1 && p[e] > p[e2]) e2 = e;

        float wn = 1.f / (p[e1] + p[e2]);
        g_tok_eid[tok * 2]     = e1;
        g_tok_eid[tok * 2 + 1] = e2;
        g_tok_w[tok * 2]       = p[e1] * wn;
        g_tok_w[tok * 2 + 1]   = p[e2] * wn;
        atomicAdd(&g_cnt[e1], 1);
        atomicAdd(&g_cnt[e2], 1);
#pragma unroll
        for (int e = 0; e < NE; e++) atomicAdd(&s_prob[e], p[e]);
        atomicAdd(&s_frac[e1], 1.f);
        atomicAdd(&s_frac[e2], 1.f);
    }
    __syncthreads();
    if (tid < NE) {
        atomicAdd(&g_probsum[tid], s_prob[tid]);
        atomicAdd(&g_fraccnt[tid], s_frac[tid]);
    }
}

// ---------------------------------------------------------------------------
// K3: scan + fill in one single-block kernel (smem atomics)
// ---------------------------------------------------------------------------
__global__ void __launch_bounds__(256) scanfill_kernel() {
    __shared__ int scur[NE];
    int tid = threadIdx.x;
    if (tid == 0) {
        int off = 0;
        for (int e = 0; e < NE; e++) {
            g_off[e] = off;
            scur[e] = off;
            off += g_cnt[e];
        }
    }
    __syncthreads();
    for (int i = tid; i < NASSIGN; i += 256) {
        int e = g_tok_eid[i];
        int slot = atomicAdd(&scur[e], 1);
        g_slot_token[slot] = i >> 1;
        g_assign_slot[i]   = slot;
    }
}

// ---------------------------------------------------------------------------
// K4: fused gate/up fp16 GEMM. 2-stage cp.async + ldmatrix (imm offsets).
//   CTA 128 x (64 gate | 64 up) x 64.  8 warps = 4m x 2n; warp 32x32 on both.
// ---------------------------------------------------------------------------
__global__ void __launch_bounds__(256, 3) gateup_kernel() {
    extern __shared__ __half sm[];
    const int ITERS = DIM / 64;   // 32

    int e   = blockIdx.z;
    int cnt = g_cnt[e];
    int m0  = blockIdx.x * 128;
    if (m0 >= cnt) return;
    int n0  = blockIdx.y * 64;
    int off = g_off[e];

    int tid  = threadIdx.x;
    int lane = tid & 31;
    int w    = tid >> 5;
    int wm   = w & 3;
    int wn   = w >> 2;
    int gid  = lane >> 2;
    int tig  = lane & 3;

    int lrow = tid >> 1;
    int lhf  = (tid & 1) * 32;

    int sidx = off + m0 + lrow;
    if (sidx > NASSIGN - 1) sidx = NASSIGN - 1;
    const __half* aptr = g_xh + (size_t)g_slot_token[sidx] * DIM + lhf;
    const __half* bptr = (lrow < 64)
        ? g_gwh + ((size_t)e * FDIM + n0 + lrow) * DIM + lhf
        : g_uwh + ((size_t)e * FDIM + n0 + (lrow - 64)) * DIM + lhf;

    uint32_t sb = smem_u32(sm);
    uint32_t sa_off  = sb + (uint32_t)(lrow * ROWB + (tid & 1) * 64);
    uint32_t sbf_off = sa_off + B_BASE_B2;

    auto issue = [&](int t, int s) {
        uint32_t sa  = sa_off + s * STAGE_B2;
        uint32_t sbb = sbf_off + s * STAGE_B2;
        const __half* ga = aptr + t * 64;
        const __half* gb = bptr + t * 64;
#pragma unroll
        for (int j = 0; j < 4; j++) CP_ASYNC16(sa + j * 16, ga + j * 8);
#pragma unroll
        for (int j = 0; j < 4; j++) CP_ASYNC16(sbb + j * 16, gb + j * 8);
        CP_COMMIT();
    };

    int lane15 = lane & 15;
    uint32_t colb = (uint32_t)((lane >> 4) * 16);
    uint32_t a_ld  = sb + (uint32_t)((wm * 32 + lane15) * ROWB) + colb;
    uint32_t bg_ld = sb + B_BASE_B2 + (uint32_t)((wn * 32 + lane15) * ROWB) + colb;

    float cg[2][4][4], cu[2][4][4];
#pragma unroll
    for (int mi = 0; mi < 2; mi++)
#pragma unroll
        for (int ni = 0; ni < 4; ni++)
#pragma unroll
            for (int q = 0; q < 4; q++) { cg[mi][ni][q] = 0.f; cu[mi][ni][q] = 0.f; }

    issue(0, 0);

#pragma unroll 1
    for (int i = 0; i < ITERS; i++) {
        if (i + 1 < ITERS) issue(i + 1, (i + 1) & 1); else CP_COMMIT();
        CP_WAIT1();
        __syncthreads();

        // Stage bases hoisted: all LDSM offsets below are compile-time imms.
        uint32_t aS = a_ld  + (uint32_t)((i & 1) * STAGE_B2);
        uint32_t bS = bg_ld + (uint32_t)((i & 1) * STAGE_B2);
#pragma unroll
        for (int kk = 0; kk < 64; kk += 16) {
            uint32_t a[2][4];
            LDSM_X4(a[0][0], a[0][1], a[0][2], a[0][3], aS + kk * 2);
            LDSM_X4(a[1][0], a[1][1], a[1][2], a[1][3], aS + kk * 2 + 16 * ROWB);

            uint32_t f0, f1, f2, f3;
            // gate rows 0-15 -> ni 0,1
            LDSM_X4(f0, f1, f2, f3, bS + kk * 2);
#pragma unroll
            for (int mi = 0; mi < 2; mi++) { mma_f16(cg[mi][0], a[mi], f0, f2);
                                             mma_f16(cg[mi][1], a[mi], f1, f3); }
            // gate rows 16-31 -> ni 2,3
            LDSM_X4(f0, f1, f2, f3, bS + kk * 2 + 16 * ROWB);
#pragma unroll
            for (int mi = 0; mi < 2; mi++) { mma_f16(cg[mi][2], a[mi], f0, f2);
                                             mma_f16(cg[mi][3], a[mi], f1, f3); }
            // up rows 64-79 -> ni 0,1
            LDSM_X4(f0, f1, f2, f3, bS + kk * 2 + 64 * ROWB);
#pragma unroll
            for (int mi = 0; mi < 2; mi++) { mma_f16(cu[mi][0], a[mi], f0, f2);
                                             mma_f16(cu[mi][1], a[mi], f1, f3); }
            // up rows 80-95 -> ni 2,3
            LDSM_X4(f0, f1, f2, f3, bS + kk * 2 + 80 * ROWB);
#pragma unroll
            for (int mi = 0; mi < 2; mi++) { mma_f16(cu[mi][2], a[mi], f0, f2);
                                             mma_f16(cu[mi][3], a[mi], f1, f3); }
        }
        __syncthreads();
    }

#pragma unroll
    for (int mi = 0; mi < 2; mi++) {
#pragma unroll
        for (int ni = 0; ni < 4; ni++) {
            int col = n0 + wn * 32 + ni * 8 + 2 * tig;
            int r0  = m0 + wm * 32 + mi * 16 + gid;
            if (r0 < cnt) {
                __half2 h = __floats2half2_rn(silu(cg[mi][ni][0]) * cu[mi][ni][0],
                                              silu(cg[mi][ni][1]) * cu[mi][ni][1]);
                *(__half2*)&g_hh[(size_t)(off + r0) * FDIM + col] = h;
            }
            if (r0 + 8 < cnt) {
                __half2 h = __floats2half2_rn(silu(cg[mi][ni][2]) * cu[mi][ni][2],
                                              silu(cg[mi][ni][3]) * cu[mi][ni][3]);
                *(__half2*)&g_hh[(size_t)(off + r0 + 8) * FDIM + col] = h;
            }
        }
    }
}

// ---------------------------------------------------------------------------
// K5: down fp16 GEMM (f32 accum). 2-stage cp.async + ldmatrix (imm offsets).
//   CTA 128x128x64, warp 32x64.
// ---------------------------------------------------------------------------
__global__ void __launch_bounds__(256, 3) down_kernel() {
    extern __shared__ __half sm[];
    const int ITERS = FDIM / 64;  // 88

    int e   = blockIdx.z;
    int cnt = g_cnt[e];
    int m0  = blockIdx.x * 128;
    if (m0 >= cnt) return;
    int n0  = blockIdx.y * 128;
    int off = g_off[e];

    int tid  = threadIdx.x;
    int lane = tid & 31;
    int w    = tid >> 5;
    int wm   = w & 3;
    int wn   = w >> 2;
    int gid  = lane >> 2;
    int tig  = lane & 3;

    int lrow = tid >> 1;
    int lhf  = (tid & 1) * 32;

    int sidx = off + m0 + lrow;
    if (sidx > NASSIGN - 1) sidx = NASSIGN - 1;
    const __half* aptr = g_hh + (size_t)sidx * FDIM + lhf;
    const __half* bptr = g_dwh + ((size_t)e * DIM + n0 + lrow) * FDIM + lhf;

    uint32_t sb = smem_u32(sm);
    uint32_t sa_off  = sb + (uint32_t)(lrow * ROWB + (tid & 1) * 64);
    uint32_t sbf_off = sa_off + B_BASE_B2;

    auto issue = [&](int t, int s) {
        uint32_t sa  = sa_off + s * STAGE_B2;
        uint32_t sbb = sbf_off + s * STAGE_B2;
        const __half* ga = aptr + t * 64;
        const __half* gb = bptr + t * 64;
#pragma unroll
        for (int j = 0; j < 4; j++) CP_ASYNC16(sa + j * 16, ga + j * 8);
#pragma unroll
        for (int j = 0; j < 4; j++) CP_ASYNC16(sbb + j * 16, gb + j * 8);
        CP_COMMIT();
    };

    int lane15 = lane & 15;
    uint32_t colb = (uint32_t)((lane >> 4) * 16);
    uint32_t a_ld = sb + (uint32_t)((wm * 32 + lane15) * ROWB) + colb;
    uint32_t b_ld = sb + B_BASE_B2 + (uint32_t)((wn * 64 + lane15) * ROWB) + colb;

    float c[2][8][4];
#pragma unroll
    for (int mi = 0; mi < 2; mi++)
#pragma unroll
        for (int ni = 0; ni < 8; ni++)
#pragma unroll
            for (int q = 0; q < 4; q++) c[mi][ni][q] = 0.f;

    issue(0, 0);

#pragma unroll 1
    for (int i = 0; i < ITERS; i++) {
        if (i + 1 < ITERS) issue(i + 1, (i + 1) & 1); else CP_COMMIT();
        CP_WAIT1();
        __syncthreads();

        uint32_t aS = a_ld + (uint32_t)((i & 1) * STAGE_B2);
        uint32_t bS = b_ld + (uint32_t)((i & 1) * STAGE_B2);
#pragma unroll
        for (int kk = 0; kk < 64; kk += 16) {
            uint32_t a[2][4];
            LDSM_X4(a[0][0], a[0][1], a[0][2], a[0][3], aS + kk * 2);
            LDSM_X4(a[1][0], a[1][1], a[1][2], a[1][3], aS + kk * 2 + 16 * ROWB);

#pragma unroll
            for (int q = 0; q < 4; q++) {
                uint32_t f0, f1, f2, f3;
                LDSM_X4(f0, f1, f2, f3, bS + kk * 2 + q * 16 * ROWB);
#pragma unroll
                for (int mi = 0; mi < 2; mi++) {
                    mma_f16(c[mi][q * 2],     a[mi], f0, f2);
                    mma_f16(c[mi][q * 2 + 1], a[mi], f1, f3);
                }
            }
        }
        __syncthreads();
    }

#pragma unroll
    for (int mi = 0; mi < 2; mi++) {
#pragma unroll
        for (int ni = 0; ni < 8; ni++) {
            int col = n0 + wn * 64 + ni * 8 + 2 * tig;
            int r0  = m0 + wm * 32 + mi * 16 + gid;
            if (r0 < cnt)
                *(float2*)&g_tmp[(size_t)(off + r0) * DIM + col] =
                    make_float2(c[mi][ni][0], c[mi][ni][1]);
            if (r0 + 8 < cnt)
                *(float2*)&g_tmp[(size_t)(off + r0 + 8) * DIM + col] =
                    make_float2(c[mi][ni][2], c[mi][ni][3]);
        }
    }
}

// ---------------------------------------------------------------------------
// K6: combine — out[t] = w0*tmp[slot0] + w1*tmp[slot1]
// ---------------------------------------------------------------------------
__global__ void __launch_bounds__(256) combine_kernel(float* __restrict__ out) {
    int t = blockIdx.x;
    int d = blockIdx.y * 1024 + threadIdx.x * 4;
    int s0 = g_assign_slot[2 * t];
    int s1 = g_assign_slot[2 * t + 1];
    float w0 = g_tok_w[2 * t];
    float w1 = g_tok_w[2 * t + 1];
    float4 a = *(const float4*)(g_tmp + (size_t)s0 * DIM + d);
    float4 b = *(const float4*)(g_tmp + (size_t)s1 * DIM + d);
    float4 o;
    o.x = w0 * a.x + w1 * b.x;
    o.y = w0 * a.y + w1 * b.y;
    o.z = w0 * a.z + w1 * b.z;
    o.w = w0 * a.w + w1 * b.w;
    *(float4*)(out + (size_t)t * DIM + d) = o;
}

// ---------------------------------------------------------------------------
// K7: aux loss scalar
// ---------------------------------------------------------------------------
__global__ void aux_kernel(float* o) {
    float a = 0.f;
    for (int e = 0; e < NE; e++)
        a += (g_probsum[e] / (float)NTOK) * (g_fraccnt[e] / (float)NTOK);
    *o = (float)NE * a;
}

// ---------------------------------------------------------------------------
// Entry
// ---------------------------------------------------------------------------
extern "C" void kernel_launch(void* const* d_in, const int* in_sizes, int n_in,
                              void* d_out, int out_size) {
    const float* x  = (const float*)d_in[0];   // [B,T,D]
    const float* rw = (const float*)d_in[1];   // [E,D]
    const float* gw = (const float*)d_in[2];   // [E,F,D]
    const float* uw = (const float*)d_in[3];   // [E,F,D]
    const float* dw = (const float*)d_in[4];   // [E,D,F]
    float* out = (float*)d_out;

    cudaFuncSetAttribute(gateup_kernel, cudaFuncAttributeMaxDynamicSharedMemorySize,
                         SMEM_BYTES);
    cudaFuncSetAttribute(down_kernel, cudaFuncAttributeMaxDynamicSharedMemorySize,
                         SMEM_BYTES);

    cvtall_kernel<<<4096, 256>>>(gw, uw, dw);
    router_kernel<<<NTOK / 8, 256>>>(x, rw);
    scanfill_kernel<<<1, 256>>>();
    gateup_kernel<<<dim3(64, FDIM / 64, NE), 256, SMEM_BYTES>>>();
    down_kernel<<<dim3(64, DIM / 128, NE), 256, SMEM_BYTES>>>();
    combine_kernel<<<dim3(NTOK, 2), 256>>>(out);
    if (out_size > NTOK * DIM)
        aux_kernel<<<1, 1>>>(out + (size_t)NTOK * DIM);
}

// round 12
// speedup vs baseline: 1.3812x; 1.3812x over previous
#include <cuda_runtime.h>
#include <cuda_fp16.h>
#include <math.h>
#include <stdint.h>

// Problem constants
#define NTOK 8192
#define DIM  2048
#define FDIM 5632
#define NE   8
#define NASSIGN (NTOK * 2)

// ---------------------------------------------------------------------------
// Scratch (device globals; no dynamic allocation allowed)
// ---------------------------------------------------------------------------
__device__ int   g_cnt[NE];
__device__ int   g_off[NE];
__device__ int   g_tok_eid[NASSIGN];
__device__ float g_tok_w[NASSIGN];
__device__ int   g_assign_slot[NASSIGN];
__device__ int   g_slot_token[NASSIGN];
__device__ float g_probsum[NE];
__device__ float g_fraccnt[NE];

__device__ __half g_xh [(size_t)NTOK * DIM];        //  34 MB: fp16 x
__device__ __half g_gwh[(size_t)NE * FDIM * DIM];   // 185 MB: fp16 gate_w
__device__ __half g_uwh[(size_t)NE * FDIM * DIM];   // 185 MB: fp16 up_w
__device__ __half g_dwh[(size_t)NE * DIM * FDIM];   // 185 MB: fp16 down_w
__device__ __half g_hh [(size_t)NASSIGN * FDIM];    // 185 MB: fp16 h
__device__ float  g_tmp[(size_t)NASSIGN * DIM];     // 134 MB: per-slot down out

// ---------------------------------------------------------------------------
// Helpers
// ---------------------------------------------------------------------------
__device__ __forceinline__ void mma_f16(float c[4], const uint32_t a[4],
                                        uint32_t b0, uint32_t b1) {
    asm volatile(
        "mma.sync.aligned.m16n8k16.row.col.f32.f16.f16.f32 "
        "{%0,%1,%2,%3}, {%4,%5,%6,%7}, {%8,%9}, {%0,%1,%2,%3};"
        : "+f"(c[0]), "+f"(c[1]), "+f"(c[2]), "+f"(c[3])
        : "r"(a[0]), "r"(a[1]), "r"(a[2]), "r"(a[3]), "r"(b0), "r"(b1));
}

#define LDSM_X4(r0, r1, r2, r3, addr) \
    asm volatile("ldmatrix.sync.aligned.m8n8.x4.shared.b16 {%0,%1,%2,%3}, [%4];" \
                 : "=r"(r0), "=r"(r1), "=r"(r2), "=r"(r3) : "r"(addr))

__device__ __forceinline__ float silu(float g) {
    return g / (1.f + __expf(-g));
}

__device__ __forceinline__ uint32_t smem_u32(const void* p) {
    uint32_t a;
    asm("{ .reg .u64 t; cvta.to.shared.u64 t, %1; cvt.u32.u64 %0, t; }"
        : "=r"(a) : "l"(p));
    return a;
}

#define CP_ASYNC16(sa, gp) \
    asm volatile("cp.async.cg.shared.global [%0], [%1], 16;" :: "r"(sa), "l"(gp))
#define CP_COMMIT() asm volatile("cp.async.commit_group;" ::: "memory")
#define CP_WAIT1()  asm volatile("cp.async.wait_group 1;" ::: "memory")

// Smem: K-slab = 64 halves (128B) per row + 16B pad -> 144B row stride.
// 3 stages: A at s*STAGE, B at 3*STAGE + s*STAGE.
#define ROWB      144
#define STAGE_B2  (128 * ROWB)                // 18432 bytes
#define B_BASE_B2 (3 * STAGE_B2)              // 55296
#define SMEM_BYTES (6 * STAGE_B2)             // 110592 bytes -> 2 CTAs/SM

// ---------------------------------------------------------------------------
// K1: merged weight cvt (gate, up, down) + counter reset
// ---------------------------------------------------------------------------
#define WN4 ((NE * FDIM * DIM) / 4)

__global__ void __launch_bounds__(256) cvtall_kernel(const float* __restrict__ gw,
                                                     const float* __restrict__ uw,
                                                     const float* __restrict__ dw) {
    if (blockIdx.x == 0 && threadIdx.x < NE) {
        g_cnt[threadIdx.x] = 0;
        g_probsum[threadIdx.x] = 0.f;
        g_fraccnt[threadIdx.x] = 0.f;
    }
    __half* gwh = g_gwh; __half* uwh = g_uwh; __half* dwh = g_dwh;
    int64_t i = (int64_t)blockIdx.x * blockDim.x + threadIdx.x;
    int64_t stride = (int64_t)gridDim.x * blockDim.x;
    const int64_t total = 3LL * WN4;
    for (; i < total; i += stride) {
        const float* src;
        __half* dst;
        int64_t j = i;
        if (j < WN4)            { src = gw; dst = gwh; }
        else if (j < 2LL * WN4) { src = uw; dst = uwh; j -= WN4; }
        else                    { src = dw; dst = dwh; j -= 2LL * WN4; }
        float4 v = ((const float4*)src)[j];
        __half2 h0 = __floats2half2_rn(v.x, v.y);
        __half2 h1 = __floats2half2_rn(v.z, v.w);
        uint2 u;
        u.x = *(const uint32_t*)&h0;
        u.y = *(const uint32_t*)&h1;
        ((uint2*)dst)[j] = u;
    }
}

// ---------------------------------------------------------------------------
// K2: router — 1 warp/token (fp32, exact); also emits fp16 x row.
// ---------------------------------------------------------------------------
__global__ void __launch_bounds__(256) router_kernel(const float* __restrict__ x,
                                                     const float* __restrict__ rw) {
    __shared__ float s_prob[NE], s_frac[NE];
    int tid = threadIdx.x;
    if (tid < NE) { s_prob[tid] = 0.f; s_frac[tid] = 0.f; }
    __syncthreads();

    int lane = tid & 31;
    int tok  = blockIdx.x * 8 + (tid >> 5);

    float acc[NE];
#pragma unroll
    for (int e = 0; e < NE; e++) acc[e] = 0.f;

    const float* xr = x + (size_t)tok * DIM;
    __half* xh = g_xh + (size_t)tok * DIM;
    for (int d = lane; d < DIM; d += 32) {
        float xv = xr[d];
        xh[d] = __float2half_rn(xv);
#pragma unroll
        for (int e = 0; e < NE; e++) acc[e] += xv * rw[e * DIM + d];
    }
#pragma unroll
    for (int e = 0; e < NE; e++) {
#pragma unroll
        for (int o = 16; o > 0; o >>= 1)
            acc[e] += __shfl_xor_sync(0xffffffffu, acc[e], o);
    }

    if (lane == 0) {
        float mx = acc[0];
#pragma unroll
        for (int e = 1; e < NE; e++) mx = fmaxf(mx, acc[e]);
        float p[NE]; float s = 0.f;
#pragma unroll
        for (int e = 0; e < NE; e++) { p[e] = expf(acc[e] - mx); s += p[e]; }
        float inv = 1.f / s;
#pragma unroll
        for (int e = 0; e < NE; e++) p[e] *= inv;

        int e1 = 0;
#pragma unroll
        for (int e = 1; e < NE; e++) if (p[e] > p[e1]) e1 = e;
        int e2 = (e1 == 0) ? 1 : 0;
#pragma unroll
        for (int e = 0; e < NE; e++) if (e != e1 && p[e] > p[e2]) e2 = e;

        float wn = 1.f / (p[e1] + p[e2]);
        g_tok_eid[tok * 2]     = e1;
        g_tok_eid[tok * 2 + 1] = e2;
        g_tok_w[tok * 2]       = p[e1] * wn;
        g_tok_w[tok * 2 + 1]   = p[e2] * wn;
        atomicAdd(&g_cnt[e1], 1);
        atomicAdd(&g_cnt[e2], 1);
#pragma unroll
        for (int e = 0; e < NE; e++) atomicAdd(&s_prob[e], p[e]);
        atomicAdd(&s_frac[e1], 1.f);
        atomicAdd(&s_frac[e2], 1.f);
    }
    __syncthreads();
    if (tid < NE) {
        atomicAdd(&g_probsum[tid], s_prob[tid]);
        atomicAdd(&g_fraccnt[tid], s_frac[tid]);
    }
}

// ---------------------------------------------------------------------------
// K3: scan + fill in one single-block kernel (smem atomics)
// ---------------------------------------------------------------------------
__global__ void __launch_bounds__(256) scanfill_kernel() {
    __shared__ int scur[NE];
    int tid = threadIdx.x;
    if (tid == 0) {
        int off = 0;
        for (int e = 0; e < NE; e++) {
            g_off[e] = off;
            scur[e] = off;
            off += g_cnt[e];
        }
    }
    __syncthreads();
    for (int i = tid; i < NASSIGN; i += 256) {
        int e = g_tok_eid[i];
        int slot = atomicAdd(&scur[e], 1);
        g_slot_token[slot] = i >> 1;
        g_assign_slot[i]   = slot;
    }
}

// ---------------------------------------------------------------------------
// K4: fused gate/up fp16 GEMM. 3-stage cp.async, ONE barrier per slab,
//   running pointers + stage counters (no div/mod, imm LDSM offsets).
//   CTA 128 x (64 gate | 64 up) x 64.  8 warps = 4m x 2n; warp 32x32 both.
// ---------------------------------------------------------------------------
__global__ void __launch_bounds__(256, 2) gateup_kernel() {
    extern __shared__ __half sm[];
    const int ITERS = DIM / 64;   // 32

    int e   = blockIdx.z;
    int cnt = g_cnt[e];
    int m0  = blockIdx.x * 128;
    if (m0 >= cnt) return;
    int n0  = blockIdx.y * 64;
    int off = g_off[e];

    int tid  = threadIdx.x;
    int lane = tid & 31;
    int w    = tid >> 5;
    int wm   = w & 3;
    int wn   = w >> 2;
    int gid  = lane >> 2;
    int tig  = lane & 3;

    int lrow = tid >> 1;

    int sidx = off + m0 + lrow;
    if (sidx > NASSIGN - 1) sidx = NASSIGN - 1;
    const __half* ga = g_xh + (size_t)g_slot_token[sidx] * DIM + (tid & 1) * 32;
    const __half* gb = (lrow < 64)
        ? g_gwh + ((size_t)e * FDIM + n0 + lrow) * DIM + (tid & 1) * 32
        : g_uwh + ((size_t)e * FDIM + n0 + (lrow - 64)) * DIM + (tid & 1) * 32;

    uint32_t sb = smem_u32(sm);
    uint32_t sa_base  = sb + (uint32_t)(lrow * ROWB + (tid & 1) * 64);
    uint32_t sbb_base = sa_base + B_BASE_B2;
    int wstage = 0;   // stage to write next

    auto issue = [&]() {
        uint32_t sa  = sa_base + wstage * STAGE_B2;
        uint32_t sbb = sbb_base + wstage * STAGE_B2;
#pragma unroll
        for (int j = 0; j < 4; j++) CP_ASYNC16(sa + j * 16, ga + j * 8);
#pragma unroll
        for (int j = 0; j < 4; j++) CP_ASYNC16(sbb + j * 16, gb + j * 8);
        CP_COMMIT();
        ga += 64; gb += 64;
        wstage = (wstage == 2) ? 0 : wstage + 1;
    };

    int lane15 = lane & 15;
    uint32_t colb = (uint32_t)((lane >> 4) * 16);
    uint32_t a_ld  = sb + (uint32_t)((wm * 32 + lane15) * ROWB) + colb;
    uint32_t bg_ld = sb + B_BASE_B2 + (uint32_t)((wn * 32 + lane15) * ROWB) + colb;

    float cg[2][4][4], cu[2][4][4];
#pragma unroll
    for (int mi = 0; mi < 2; mi++)
#pragma unroll
        for (int ni = 0; ni < 4; ni++)
#pragma unroll
            for (int q = 0; q < 4; q++) { cg[mi][ni][q] = 0.f; cu[mi][ni][q] = 0.f; }

    issue();
    issue();

    int rstage = 0;   // stage to read
#pragma unroll 1
    for (int i = 0; i < ITERS; i++) {
        CP_WAIT1();
        __syncthreads();
        if (i + 2 < ITERS) issue(); else CP_COMMIT();

        uint32_t aS = a_ld  + (uint32_t)(rstage * STAGE_B2);
        uint32_t bS = bg_ld + (uint32_t)(rstage * STAGE_B2);
        rstage = (rstage == 2) ? 0 : rstage + 1;
#pragma unroll
        for (int kk = 0; kk < 64; kk += 16) {
            uint32_t a[2][4];
            LDSM_X4(a[0][0], a[0][1], a[0][2], a[0][3], aS + kk * 2);
            LDSM_X4(a[1][0], a[1][1], a[1][2], a[1][3], aS + kk * 2 + 16 * ROWB);

            uint32_t f0, f1, f2, f3;
            // gate rows 0-15 -> ni 0,1
            LDSM_X4(f0, f1, f2, f3, bS + kk * 2);
#pragma unroll
            for (int mi = 0; mi < 2; mi++) { mma_f16(cg[mi][0], a[mi], f0, f2);
                                             mma_f16(cg[mi][1], a[mi], f1, f3); }
            // gate rows 16-31 -> ni 2,3
            LDSM_X4(f0, f1, f2, f3, bS + kk * 2 + 16 * ROWB);
#pragma unroll
            for (int mi = 0; mi < 2; mi++) { mma_f16(cg[mi][2], a[mi], f0, f2);
                                             mma_f16(cg[mi][3], a[mi], f1, f3); }
            // up rows 64-79 -> ni 0,1
            LDSM_X4(f0, f1, f2, f3, bS + kk * 2 + 64 * ROWB);
#pragma unroll
            for (int mi = 0; mi < 2; mi++) { mma_f16(cu[mi][0], a[mi], f0, f2);
                                             mma_f16(cu[mi][1], a[mi], f1, f3); }
            // up rows 80-95 -> ni 2,3
            LDSM_X4(f0, f1, f2, f3, bS + kk * 2 + 80 * ROWB);
#pragma unroll
            for (int mi = 0; mi < 2; mi++) { mma_f16(cu[mi][2], a[mi], f0, f2);
                                             mma_f16(cu[mi][3], a[mi], f1, f3); }
        }
        // No trailing barrier: the leading __syncthreads of iter i+1 plus
        // issue-after-sync ordering protects stage reuse (3-stage proof).
    }

#pragma unroll
    for (int mi = 0; mi < 2; mi++) {
#pragma unroll
        for (int ni = 0; ni < 4; ni++) {
            int col = n0 + wn * 32 + ni * 8 + 2 * tig;
            int r0  = m0 + wm * 32 + mi * 16 + gid;
            if (r0 < cnt) {
                __half2 h = __floats2half2_rn(silu(cg[mi][ni][0]) * cu[mi][ni][0],
                                              silu(cg[mi][ni][1]) * cu[mi][ni][1]);
                *(__half2*)&g_hh[(size_t)(off + r0) * FDIM + col] = h;
            }
            if (r0 + 8 < cnt) {
                __half2 h = __floats2half2_rn(silu(cg[mi][ni][2]) * cu[mi][ni][2],
                                              silu(cg[mi][ni][3]) * cu[mi][ni][3]);
                *(__half2*)&g_hh[(size_t)(off + r0 + 8) * FDIM + col] = h;
            }
        }
    }
}

// ---------------------------------------------------------------------------
// K5: down fp16 GEMM (f32 accum). 3-stage cp.async, one barrier per slab.
//   CTA 128x128x64, warp 32x64.
// ---------------------------------------------------------------------------
__global__ void __launch_bounds__(256, 2) down_kernel() {
    extern __shared__ __half sm[];
    const int ITERS = FDIM / 64;  // 88

    int e   = blockIdx.z;
    int cnt = g_cnt[e];
    int m0  = blockIdx.x * 128;
    if (m0 >= cnt) return;
    int n0  = blockIdx.y * 128;
    int off = g_off[e];

    int tid  = threadIdx.x;
    int lane = tid & 31;
    int w    = tid >> 5;
    int wm   = w & 3;
    int wn   = w >> 2;
    int gid  = lane >> 2;
    int tig  = lane & 3;

    int lrow = tid >> 1;

    int sidx = off + m0 + lrow;
    if (sidx > NASSIGN - 1) sidx = NASSIGN - 1;
    const __half* ga = g_hh + (size_t)sidx * FDIM + (tid & 1) * 32;
    const __half* gb = g_dwh + ((size_t)e * DIM + n0 + lrow) * FDIM + (tid & 1) * 32;

    uint32_t sb = smem_u32(sm);
    uint32_t sa_base  = sb + (uint32_t)(lrow * ROWB + (tid & 1) * 64);
    uint32_t sbb_base = sa_base + B_BASE_B2;
    int wstage = 0;

    auto issue = [&]() {
        uint32_t sa  = sa_base + wstage * STAGE_B2;
        uint32_t sbb = sbb_base + wstage * STAGE_B2;
#pragma unroll
        for (int j = 0; j < 4; j++) CP_ASYNC16(sa + j * 16, ga + j * 8);
#pragma unroll
        for (int j = 0; j < 4; j++) CP_ASYNC16(sbb + j * 16, gb + j * 8);
        CP_COMMIT();
        ga += 64; gb += 64;
        wstage = (wstage == 2) ? 0 : wstage + 1;
    };

    int lane15 = lane & 15;
    uint32_t colb = (uint32_t)((lane >> 4) * 16);
    uint32_t a_ld = sb + (uint32_t)((wm * 32 + lane15) * ROWB) + colb;
    uint32_t b_ld = sb + B_BASE_B2 + (uint32_t)((wn * 64 + lane15) * ROWB) + colb;

    float c[2][8][4];
#pragma unroll
    for (int mi = 0; mi < 2; mi++)
#pragma unroll
        for (int ni = 0; ni < 8; ni++)
#pragma unroll
            for (int q = 0; q < 4; q++) c[mi][ni][q] = 0.f;

    issue();
    issue();

    int rstage = 0;
#pragma unroll 1
    for (int i = 0; i < ITERS; i++) {
        CP_WAIT1();
        __syncthreads();
        if (i + 2 < ITERS) issue(); else CP_COMMIT();

        uint32_t aS = a_ld + (uint32_t)(rstage * STAGE_B2);
        uint32_t bS = b_ld + (uint32_t)(rstage * STAGE_B2);
        rstage = (rstage == 2) ? 0 : rstage + 1;
#pragma unroll
        for (int kk = 0; kk < 64; kk += 16) {
            uint32_t a[2][4];
            LDSM_X4(a[0][0], a[0][1], a[0][2], a[0][3], aS + kk * 2);
            LDSM_X4(a[1][0], a[1][1], a[1][2], a[1][3], aS + kk * 2 + 16 * ROWB);

#pragma unroll
            for (int q = 0; q < 4; q++) {
                uint32_t f0, f1, f2, f3;
                LDSM_X4(f0, f1, f2, f3, bS + kk * 2 + q * 16 * ROWB);
#pragma unroll
                for (int mi = 0; mi < 2; mi++) {
                    mma_f16(c[mi][q * 2],     a[mi], f0, f2);
                    mma_f16(c[mi][q * 2 + 1], a[mi], f1, f3);
                }
            }
        }
    }

#pragma unroll
    for (int mi = 0; mi < 2; mi++) {
#pragma unroll
        for (int ni = 0; ni < 8; ni++) {
            int col = n0 + wn * 64 + ni * 8 + 2 * tig;
            int r0  = m0 + wm * 32 + mi * 16 + gid;
            if (r0 < cnt)
                *(float2*)&g_tmp[(size_t)(off + r0) * DIM + col] =
                    make_float2(c[mi][ni][0], c[mi][ni][1]);
            if (r0 + 8 < cnt)
                *(float2*)&g_tmp[(size_t)(off + r0 + 8) * DIM + col] =
                    make_float2(c[mi][ni][2], c[mi][ni][3]);
        }
    }
}

// ---------------------------------------------------------------------------
// K6: combine — out[t] = w0*tmp[slot0] + w1*tmp[slot1]
// ---------------------------------------------------------------------------
__global__ void __launch_bounds__(256) combine_kernel(float* __restrict__ out) {
    int t = blockIdx.x;
    int d = blockIdx.y * 1024 + threadIdx.x * 4;
    int s0 = g_assign_slot[2 * t];
    int s1 = g_assign_slot[2 * t + 1];
    float w0 = g_tok_w[2 * t];
    float w1 = g_tok_w[2 * t + 1];
    float4 a = *(const float4*)(g_tmp + (size_t)s0 * DIM + d);
    float4 b = *(const float4*)(g_tmp + (size_t)s1 * DIM + d);
    float4 o;
    o.x = w0 * a.x + w1 * b.x;
    o.y = w0 * a.y + w1 * b.y;
    o.z = w0 * a.z + w1 * b.z;
    o.w = w0 * a.w + w1 * b.w;
    *(float4*)(out + (size_t)t * DIM + d) = o;
}

// ---------------------------------------------------------------------------
// K7: aux loss scalar
// ---------------------------------------------------------------------------
__global__ void aux_kernel(float* o) {
    float a = 0.f;
    for (int e = 0; e < NE; e++)
        a += (g_probsum[e] / (float)NTOK) * (g_fraccnt[e] / (float)NTOK);
    *o = (float)NE * a;
}

// ---------------------------------------------------------------------------
// Entry
// ---------------------------------------------------------------------------
extern "C" void kernel_launch(void* const* d_in, const int* in_sizes, int n_in,
                              void* d_out, int out_size) {
    const float* x  = (const float*)d_in[0];   // [B,T,D]
    const float* rw = (const float*)d_in[1];   // [E,D]
    const float* gw = (const float*)d_in[2];   // [E,F,D]
    const float* uw = (const float*)d_in[3];   // [E,F,D]
    const float* dw = (const float*)d_in[4];   // [E,D,F]
    float* out = (float*)d_out;

    cudaFuncSetAttribute(gateup_kernel, cudaFuncAttributeMaxDynamicSharedMemorySize,
                         SMEM_BYTES);
    cudaFuncSetAttribute(down_kernel, cudaFuncAttributeMaxDynamicSharedMemorySize,
                         SMEM_BYTES);

    cvtall_kernel<<<4096, 256>>>(gw, uw, dw);
    router_kernel<<<NTOK / 8, 256>>>(x, rw);
    scanfill_kernel<<<1, 256>>>();
    gateup_kernel<<<dim3(64, FDIM / 64, NE), 256, SMEM_BYTES>>>();
    down_kernel<<<dim3(64, DIM / 128, NE), 256, SMEM_BYTES>>>();
    combine_kernel<<<dim3(NTOK, 2), 256>>>(out);
    if (out_size > NTOK * DIM)
        aux_kernel<<<1, 1>>>(out + (size_t)NTOK * DIM);
}

// round 13
// speedup vs baseline: 1.3925x; 1.0082x over previous
#include <cuda_runtime.h>
#include <cuda_fp16.h>
#include <math.h>
#include <stdint.h>

// Problem constants
#define NTOK 8192
#define DIM  2048
#define FDIM 5632
#define NE   8
#define NASSIGN (NTOK * 2)

// ---------------------------------------------------------------------------
// Scratch (device globals; no dynamic allocation allowed)
// ---------------------------------------------------------------------------
__device__ int   g_cnt[NE];
__device__ int   g_off[NE];
__device__ int   g_tok_eid[NASSIGN];
__device__ float g_tok_w[NASSIGN];
__device__ int   g_assign_slot[NASSIGN];
__device__ int   g_slot_token[NASSIGN];
__device__ float g_probsum[NE];
__device__ float g_fraccnt[NE];

__device__ __half g_xh [(size_t)NTOK * DIM];        //  34 MB: fp16 x
__device__ __half g_gwh[(size_t)NE * FDIM * DIM];   // 185 MB: fp16 gate_w
__device__ __half g_uwh[(size_t)NE * FDIM * DIM];   // 185 MB: fp16 up_w
__device__ __half g_dwh[(size_t)NE * DIM * FDIM];   // 185 MB: fp16 down_w
__device__ __half g_hh [(size_t)NASSIGN * FDIM];    // 185 MB: fp16 h
__device__ float  g_tmp[(size_t)NASSIGN * DIM];     // 134 MB: per-slot down out

// ---------------------------------------------------------------------------
// Helpers
// ---------------------------------------------------------------------------
__device__ __forceinline__ void mma_f16(float c[4], const uint32_t a[4],
                                        uint32_t b0, uint32_t b1) {
    asm volatile(
        "mma.sync.aligned.m16n8k16.row.col.f32.f16.f16.f32 "
        "{%0,%1,%2,%3}, {%4,%5,%6,%7}, {%8,%9}, {%0,%1,%2,%3};"
        : "+f"(c[0]), "+f"(c[1]), "+f"(c[2]), "+f"(c[3])
        : "r"(a[0]), "r"(a[1]), "r"(a[2]), "r"(a[3]), "r"(b0), "r"(b1));
}

#define LDSM_X4(r0, r1, r2, r3, addr) \
    asm volatile("ldmatrix.sync.aligned.m8n8.x4.shared.b16 {%0,%1,%2,%3}, [%4];" \
                 : "=r"(r0), "=r"(r1), "=r"(r2), "=r"(r3) : "r"(addr))

__device__ __forceinline__ float silu(float g) {
    return g / (1.f + __expf(-g));
}

__device__ __forceinline__ uint32_t smem_u32(const void* p) {
    uint32_t a;
    asm("{ .reg .u64 t; cvta.to.shared.u64 t, %1; cvt.u32.u64 %0, t; }"
        : "=r"(a) : "l"(p));
    return a;
}

#define CP_ASYNC16(sa, gp) \
    asm volatile("cp.async.cg.shared.global [%0], [%1], 16;" :: "r"(sa), "l"(gp))
#define CP_COMMIT() asm volatile("cp.async.commit_group;" ::: "memory")
#define CP_WAIT1()  asm volatile("cp.async.wait_group 1;" ::: "memory")

// Smem: K-slab = 64 halves (128B) per row + 16B pad -> 144B row stride.
// Stage = A tile (128 rows) + B tile (256 rows). 3 stages, 1 CTA/SM.
#define ROWB      144
#define A_BYTES   (128 * ROWB)                // 18432
#define B_BYTES   (256 * ROWB)                // 36864
#define STAGE     (A_BYTES + B_BYTES)         // 55296
#define SMEM_BYTES (3 * STAGE)                // 165888

// ---------------------------------------------------------------------------
// K1: merged weight cvt (gate, up, down) + counter reset
// ---------------------------------------------------------------------------
#define WN4 ((NE * FDIM * DIM) / 4)

__global__ void __launch_bounds__(256) cvtall_kernel(const float* __restrict__ gw,
                                                     const float* __restrict__ uw,
                                                     const float* __restrict__ dw) {
    if (blockIdx.x == 0 && threadIdx.x < NE) {
        g_cnt[threadIdx.x] = 0;
        g_probsum[threadIdx.x] = 0.f;
        g_fraccnt[threadIdx.x] = 0.f;
    }
    __half* gwh = g_gwh; __half* uwh = g_uwh; __half* dwh = g_dwh;
    int64_t i = (int64_t)blockIdx.x * blockDim.x + threadIdx.x;
    int64_t stride = (int64_t)gridDim.x * blockDim.x;
    const int64_t total = 3LL * WN4;
    for (; i < total; i += stride) {
        const float* src;
        __half* dst;
        int64_t j = i;
        if (j < WN4)            { src = gw; dst = gwh; }
        else if (j < 2LL * WN4) { src = uw; dst = uwh; j -= WN4; }
        else                    { src = dw; dst = dwh; j -= 2LL * WN4; }
        float4 v = ((const float4*)src)[j];
        __half2 h0 = __floats2half2_rn(v.x, v.y);
        __half2 h1 = __floats2half2_rn(v.z, v.w);
        uint2 u;
        u.x = *(const uint32_t*)&h0;
        u.y = *(const uint32_t*)&h1;
        ((uint2*)dst)[j] = u;
    }
}

// ---------------------------------------------------------------------------
// K2: router — 1 warp/token (fp32, exact); also emits fp16 x row.
// ---------------------------------------------------------------------------
__global__ void __launch_bounds__(256) router_kernel(const float* __restrict__ x,
                                                     const float* __restrict__ rw) {
    __shared__ float s_prob[NE], s_frac[NE];
    int tid = threadIdx.x;
    if (tid < NE) { s_prob[tid] = 0.f; s_frac[tid] = 0.f; }
    __syncthreads();

    int lane = tid & 31;
    int tok  = blockIdx.x * 8 + (tid >> 5);

    float acc[NE];
#pragma unroll
    for (int e = 0; e < NE; e++) acc[e] = 0.f;

    const float* xr = x + (size_t)tok * DIM;
    __half* xh = g_xh + (size_t)tok * DIM;
    for (int d = lane; d < DIM; d += 32) {
        float xv = xr[d];
        xh[d] = __float2half_rn(xv);
#pragma unroll
        for (int e = 0; e < NE; e++) acc[e] += xv * rw[e * DIM + d];
    }
#pragma unroll
    for (int e = 0; e < NE; e++) {
#pragma unroll
        for (int o = 16; o > 0; o >>= 1)
            acc[e] += __shfl_xor_sync(0xffffffffu, acc[e], o);
    }

    if (lane == 0) {
        float mx = acc[0];
#pragma unroll
        for (int e = 1; e < NE; e++) mx = fmaxf(mx, acc[e]);
        float p[NE]; float s = 0.f;
#pragma unroll
        for (int e = 0; e < NE; e++) { p[e] = expf(acc[e] - mx); s += p[e]; }
        float inv = 1.f / s;
#pragma unroll
        for (int e = 0; e < NE; e++) p[e] *= inv;

        int e1 = 0;
#pragma unroll
        for (int e = 1; e < NE; e++) if (p[e] > p[e1]) e1 = e;
        int e2 = (e1 == 0) ? 1 : 0;
#pragma unroll
        for (int e = 0; e < NE; e++) if (e != e1 && p[e] > p[e2]) e2 = e;

        float wn = 1.f / (p[e1] + p[e2]);
        g_tok_eid[tok * 2]     = e1;
        g_tok_eid[tok * 2 + 1] = e2;
        g_tok_w[tok * 2]       = p[e1] * wn;
        g_tok_w[tok * 2 + 1]   = p[e2] * wn;
        atomicAdd(&g_cnt[e1], 1);
        atomicAdd(&g_cnt[e2], 1);
#pragma unroll
        for (int e = 0; e < NE; e++) atomicAdd(&s_prob[e], p[e]);
        atomicAdd(&s_frac[e1], 1.f);
        atomicAdd(&s_frac[e2], 1.f);
    }
    __syncthreads();
    if (tid < NE) {
        atomicAdd(&g_probsum[tid], s_prob[tid]);
        atomicAdd(&g_fraccnt[tid], s_frac[tid]);
    }
}

// ---------------------------------------------------------------------------
// K3: scan + fill in one single-block kernel (smem atomics)
// ---------------------------------------------------------------------------
__global__ void __launch_bounds__(256) scanfill_kernel() {
    __shared__ int scur[NE];
    int tid = threadIdx.x;
    if (tid == 0) {
        int off = 0;
        for (int e = 0; e < NE; e++) {
            g_off[e] = off;
            scur[e] = off;
            off += g_cnt[e];
        }
    }
    __syncthreads();
    for (int i = tid; i < NASSIGN; i += 256) {
        int e = g_tok_eid[i];
        int slot = atomicAdd(&scur[e], 1);
        g_slot_token[slot] = i >> 1;
        g_assign_slot[i]   = slot;
    }
}

// ---------------------------------------------------------------------------
// K4: fused gate/up fp16 GEMM, 64x64 warp tiles (128 B smem per mma).
//   CTA 128m x (128 gate | 128 up), 8 warps = 2m x 4n; warp 64m x (32g|32u).
//   3-stage cp.async, one barrier per slab, 1 CTA/SM.
// ---------------------------------------------------------------------------
__global__ void __launch_bounds__(256, 1) gateup_kernel() {
    extern __shared__ __half sm[];
    const int ITERS = DIM / 64;   // 32

    int e   = blockIdx.z;
    int cnt = g_cnt[e];
    int m0  = blockIdx.x * 128;
    if (m0 >= cnt) return;
    int n0  = blockIdx.y * 128;
    int off = g_off[e];

    int tid  = threadIdx.x;
    int lane = tid & 31;
    int w    = tid >> 5;
    int wm   = w & 1;           // 2 m-positions * 64 rows
    int wn   = w >> 1;          // 4 n-positions * 32 cols (gate; up mirrors)
    int gid  = lane >> 2;
    int tig  = lane & 3;

    int lrow = tid >> 1;        // 0..127

    int sidx = off + m0 + lrow;
    if (sidx > NASSIGN - 1) sidx = NASSIGN - 1;
    const __half* ga = g_xh + (size_t)g_slot_token[sidx] * DIM + (tid & 1) * 32;
    const __half* gg = g_gwh + ((size_t)e * FDIM + n0 + lrow) * DIM + (tid & 1) * 32;
    const __half* gu = g_uwh + ((size_t)e * FDIM + n0 + lrow) * DIM + (tid & 1) * 32;

    uint32_t sb = smem_u32(sm);
    uint32_t sa_base  = sb + (uint32_t)(lrow * ROWB + (tid & 1) * 64);
    uint32_t sbg_base = sa_base + A_BYTES;            // gate rows 0-127
    uint32_t sbu_base = sbg_base + 128 * ROWB;        // up rows 128-255
    int wstage = 0;

    auto issue = [&]() {
        uint32_t st = (uint32_t)(wstage * STAGE);
#pragma unroll
        for (int j = 0; j < 4; j++) CP_ASYNC16(sa_base + st + j * 16, ga + j * 8);
#pragma unroll
        for (int j = 0; j < 4; j++) CP_ASYNC16(sbg_base + st + j * 16, gg + j * 8);
#pragma unroll
        for (int j = 0; j < 4; j++) CP_ASYNC16(sbu_base + st + j * 16, gu + j * 8);
        CP_COMMIT();
        ga += 64; gg += 64; gu += 64;
        wstage = (wstage == 2) ? 0 : wstage + 1;
    };

    int lane15 = lane & 15;
    uint32_t colb = (uint32_t)((lane >> 4) * 16);
    uint32_t a_ld = sb + (uint32_t)((wm * 64 + lane15) * ROWB) + colb;
    uint32_t b_ld = sb + A_BYTES + (uint32_t)((wn * 32 + lane15) * ROWB) + colb;

    float cg[4][4][4], cu[4][4][4];
#pragma unroll
    for (int mi = 0; mi < 4; mi++)
#pragma unroll
        for (int ni = 0; ni < 4; ni++)
#pragma unroll
            for (int q = 0; q < 4; q++) { cg[mi][ni][q] = 0.f; cu[mi][ni][q] = 0.f; }

    issue();
    issue();

    int rstage = 0;
#pragma unroll 1
    for (int i = 0; i < ITERS; i++) {
        CP_WAIT1();
        __syncthreads();
        if (i + 2 < ITERS) issue(); else CP_COMMIT();

        uint32_t aS = a_ld + (uint32_t)(rstage * STAGE);
        uint32_t bS = b_ld + (uint32_t)(rstage * STAGE);
        rstage = (rstage == 2) ? 0 : rstage + 1;
#pragma unroll
        for (int kk = 0; kk < 64; kk += 16) {
            uint32_t a[4][4];
#pragma unroll
            for (int mi = 0; mi < 4; mi++)
                LDSM_X4(a[mi][0], a[mi][1], a[mi][2], a[mi][3],
                        aS + kk * 2 + mi * 16 * ROWB);

            uint32_t f0, f1, f2, f3;
#pragma unroll
            for (int q = 0; q < 2; q++) {     // gate halves
                LDSM_X4(f0, f1, f2, f3, bS + kk * 2 + q * 16 * ROWB);
#pragma unroll
                for (int mi = 0; mi < 4; mi++) {
                    mma_f16(cg[mi][q * 2],     a[mi], f0, f2);
                    mma_f16(cg[mi][q * 2 + 1], a[mi], f1, f3);
                }
            }
#pragma unroll
            for (int q = 0; q < 2; q++) {     // up halves (+128 rows)
                LDSM_X4(f0, f1, f2, f3, bS + kk * 2 + (128 + q * 16) * ROWB);
#pragma unroll
                for (int mi = 0; mi < 4; mi++) {
                    mma_f16(cu[mi][q * 2],     a[mi], f0, f2);
                    mma_f16(cu[mi][q * 2 + 1], a[mi], f1, f3);
                }
            }
        }
    }

#pragma unroll
    for (int mi = 0; mi < 4; mi++) {
#pragma unroll
        for (int ni = 0; ni < 4; ni++) {
            int col = n0 + wn * 32 + ni * 8 + 2 * tig;
            int r0  = m0 + wm * 64 + mi * 16 + gid;
            if (r0 < cnt) {
                __half2 h = __floats2half2_rn(silu(cg[mi][ni][0]) * cu[mi][ni][0],
                                              silu(cg[mi][ni][1]) * cu[mi][ni][1]);
                *(__half2*)&g_hh[(size_t)(off + r0) * FDIM + col] = h;
            }
            if (r0 + 8 < cnt) {
                __half2 h = __floats2half2_rn(silu(cg[mi][ni][2]) * cu[mi][ni][2],
                                              silu(cg[mi][ni][3]) * cu[mi][ni][3]);
                *(__half2*)&g_hh[(size_t)(off + r0 + 8) * FDIM + col] = h;
            }
        }
    }
}

// ---------------------------------------------------------------------------
// K5: down fp16 GEMM (f32 accum), 64x64 warp tiles.
//   CTA 128m x 256n, 8 warps = 2m x 4n; warp 64x64. 3-stage cp.async.
// ---------------------------------------------------------------------------
__global__ void __launch_bounds__(256, 1) down_kernel() {
    extern __shared__ __half sm[];
    const int ITERS = FDIM / 64;  // 88

    int e   = blockIdx.z;
    int cnt = g_cnt[e];
    int m0  = blockIdx.x * 128;
    if (m0 >= cnt) return;
    int n0  = blockIdx.y * 256;
    int off = g_off[e];

    int tid  = threadIdx.x;
    int lane = tid & 31;
    int w    = tid >> 5;
    int wm   = w & 1;
    int wn   = w >> 1;          // 4 n-positions * 64 cols
    int gid  = lane >> 2;
    int tig  = lane & 3;

    int lrow = tid >> 1;

    int sidx = off + m0 + lrow;
    if (sidx > NASSIGN - 1) sidx = NASSIGN - 1;
    const __half* ga  = g_hh + (size_t)sidx * FDIM + (tid & 1) * 32;
    const __half* gb0 = g_dwh + ((size_t)e * DIM + n0 + lrow) * FDIM + (tid & 1) * 32;
    const __half* gb1 = gb0 + (size_t)128 * FDIM;

    uint32_t sb = smem_u32(sm);
    uint32_t sa_base  = sb + (uint32_t)(lrow * ROWB + (tid & 1) * 64);
    uint32_t sb0_base = sa_base + A_BYTES;
    uint32_t sb1_base = sb0_base + 128 * ROWB;
    int wstage = 0;

    auto issue = [&]() {
        uint32_t st = (uint32_t)(wstage * STAGE);
#pragma unroll
        for (int j = 0; j < 4; j++) CP_ASYNC16(sa_base + st + j * 16, ga + j * 8);
#pragma unroll
        for (int j = 0; j < 4; j++) CP_ASYNC16(sb0_base + st + j * 16, gb0 + j * 8);
#pragma unroll
        for (int j = 0; j < 4; j++) CP_ASYNC16(sb1_base + st + j * 16, gb1 + j * 8);
        CP_COMMIT();
        ga += 64; gb0 += 64; gb1 += 64;
        wstage = (wstage == 2) ? 0 : wstage + 1;
    };

    int lane15 = lane & 15;
    uint32_t colb = (uint32_t)((lane >> 4) * 16);
    uint32_t a_ld = sb + (uint32_t)((wm * 64 + lane15) * ROWB) + colb;
    uint32_t b_ld = sb + A_BYTES + (uint32_t)((wn * 64 + lane15) * ROWB) + colb;

    float c[4][8][4];
#pragma unroll
    for (int mi = 0; mi < 4; mi++)
#pragma unroll
        for (int ni = 0; ni < 8; ni++)
#pragma unroll
            for (int q = 0; q < 4; q++) c[mi][ni][q] = 0.f;

    issue();
    issue();

    int rstage = 0;
#pragma unroll 1
    for (int i = 0; i < ITERS; i++) {
        CP_WAIT1();
        __syncthreads();
        if (i + 2 < ITERS) issue(); else CP_COMMIT();

        uint32_t aS = a_ld + (uint32_t)(rstage * STAGE);
        uint32_t bS = b_ld + (uint32_t)(rstage * STAGE);
        rstage = (rstage == 2) ? 0 : rstage + 1;
#pragma unroll
        for (int kk = 0; kk < 64; kk += 16) {
            uint32_t a[4][4];
#pragma unroll
            for (int mi = 0; mi < 4; mi++)
                LDSM_X4(a[mi][0], a[mi][1], a[mi][2], a[mi][3],
                        aS + kk * 2 + mi * 16 * ROWB);

#pragma unroll
            for (int q = 0; q < 4; q++) {
                uint32_t f0, f1, f2, f3;
                LDSM_X4(f0, f1, f2, f3, bS + kk * 2 + q * 16 * ROWB);
#pragma unroll
                for (int mi = 0; mi < 4; mi++) {
                    mma_f16(c[mi][q * 2],     a[mi], f0, f2);
                    mma_f16(c[mi][q * 2 + 1], a[mi], f1, f3);
                }
            }
        }
    }

#pragma unroll
    for (int mi = 0; mi < 4; mi++) {
#pragma unroll
        for (int ni = 0; ni < 8; ni++) {
            int col = n0 + wn * 64 + ni * 8 + 2 * tig;
            int r0  = m0 + wm * 64 + mi * 16 + gid;
            if (r0 < cnt)
                *(float2*)&g_tmp[(size_t)(off + r0) * DIM + col] =
                    make_float2(c[mi][ni][0], c[mi][ni][1]);
            if (r0 + 8 < cnt)
                *(float2*)&g_tmp[(size_t)(off + r0 + 8) * DIM + col] =
                    make_float2(c[mi][ni][2], c[mi][ni][3]);
        }
    }
}

// ---------------------------------------------------------------------------
// K6: combine — out[t] = w0*tmp[slot0] + w1*tmp[slot1]
// ---------------------------------------------------------------------------
__global__ void __launch_bounds__(256) combine_kernel(float* __restrict__ out) {
    int t = blockIdx.x;
    int d = blockIdx.y * 1024 + threadIdx.x * 4;
    int s0 = g_assign_slot[2 * t];
    int s1 = g_assign_slot[2 * t + 1];
    float w0 = g_tok_w[2 * t];
    float w1 = g_tok_w[2 * t + 1];
    float4 a = *(const float4*)(g_tmp + (size_t)s0 * DIM + d);
    float4 b = *(const float4*)(g_tmp + (size_t)s1 * DIM + d);
    float4 o;
    o.x = w0 * a.x + w1 * b.x;
    o.y = w0 * a.y + w1 * b.y;
    o.z = w0 * a.z + w1 * b.z;
    o.w = w0 * a.w + w1 * b.w;
    *(float4*)(out + (size_t)t * DIM + d) = o;
}

// ---------------------------------------------------------------------------
// K7: aux loss scalar
// ---------------------------------------------------------------------------
__global__ void aux_kernel(float* o) {
    float a = 0.f;
    for (int e = 0; e < NE; e++)
        a += (g_probsum[e] / (float)NTOK) * (g_fraccnt[e] / (float)NTOK);
    *o = (float)NE * a;
}

// ---------------------------------------------------------------------------
// Entry
// ---------------------------------------------------------------------------
extern "C" void kernel_launch(void* const* d_in, const int* in_sizes, int n_in,
                              void* d_out, int out_size) {
    const float* x  = (const float*)d_in[0];   // [B,T,D]
    const float* rw = (const float*)d_in[1];   // [E,D]
    const float* gw = (const float*)d_in[2];   // [E,F,D]
    const float* uw = (const float*)d_in[3];   // [E,F,D]
    const float* dw = (const float*)d_in[4];   // [E,D,F]
    float* out = (float*)d_out;

    cudaFuncSetAttribute(gateup_kernel, cudaFuncAttributeMaxDynamicSharedMemorySize,
                         SMEM_BYTES);
    cudaFuncSetAttribute(down_kernel, cudaFuncAttributeMaxDynamicSharedMemorySize,
                         SMEM_BYTES);

    cvtall_kernel<<<4096, 256>>>(gw, uw, dw);
    router_kernel<<<NTOK / 8, 256>>>(x, rw);
    scanfill_kernel<<<1, 256>>>();
    gateup_kernel<<<dim3(64, FDIM / 128, NE), 256, SMEM_BYTES>>>();
    down_kernel<<<dim3(64, DIM / 256, NE), 256, SMEM_BYTES>>>();
    combine_kernel<<<dim3(NTOK, 2), 256>>>(out);
    if (out_size > NTOK * DIM)
        aux_kernel<<<1, 1>>>(out + (size_t)NTOK * DIM);
}

// round 14
// speedup vs baseline: 1.3976x; 1.0036x over previous
#include <cuda_runtime.h>
#include <cuda_fp16.h>
#include <math.h>
#include <stdint.h>

// Problem constants
#define NTOK 8192
#define DIM  2048
#define FDIM 5632
#define NE   8
#define NASSIGN (NTOK * 2)

// ---------------------------------------------------------------------------
// Scratch (device globals; no dynamic allocation allowed)
// ---------------------------------------------------------------------------
__device__ int   g_cnt[NE];
__device__ int   g_off[NE];
__device__ int   g_tok_eid[NASSIGN];
__device__ float g_tok_w[NASSIGN];
__device__ int   g_assign_slot[NASSIGN];
__device__ int   g_slot_token[NASSIGN];
__device__ float g_probsum[NE];
__device__ float g_fraccnt[NE];

__device__ __half g_xh [(size_t)NTOK * DIM];        //  34 MB: fp16 x
__device__ __half g_gwh[(size_t)NE * FDIM * DIM];   // 185 MB: fp16 gate_w
__device__ __half g_uwh[(size_t)NE * FDIM * DIM];   // 185 MB: fp16 up_w
__device__ __half g_dwh[(size_t)NE * DIM * FDIM];   // 185 MB: fp16 down_w
__device__ __half g_hh [(size_t)NASSIGN * FDIM];    // 185 MB: fp16 h
__device__ float  g_tmp[(size_t)NASSIGN * DIM];     // 134 MB: per-slot down out

// ---------------------------------------------------------------------------
// Helpers
// ---------------------------------------------------------------------------
__device__ __forceinline__ void mma_f16(float c[4], const uint32_t a[4],
                                        uint32_t b0, uint32_t b1) {
    asm volatile(
        "mma.sync.aligned.m16n8k16.row.col.f32.f16.f16.f32 "
        "{%0,%1,%2,%3}, {%4,%5,%6,%7}, {%8,%9}, {%0,%1,%2,%3};"
        : "+f"(c[0]), "+f"(c[1]), "+f"(c[2]), "+f"(c[3])
        : "r"(a[0]), "r"(a[1]), "r"(a[2]), "r"(a[3]), "r"(b0), "r"(b1));
}

#define LDSM_X4(r0, r1, r2, r3, addr) \
    asm volatile("ldmatrix.sync.aligned.m8n8.x4.shared.b16 {%0,%1,%2,%3}, [%4];" \
                 : "=r"(r0), "=r"(r1), "=r"(r2), "=r"(r3) : "r"(addr))

__device__ __forceinline__ float silu(float g) {
    return g / (1.f + __expf(-g));
}

__device__ __forceinline__ uint32_t smem_u32(const void* p) {
    uint32_t a;
    asm("{ .reg .u64 t; cvta.to.shared.u64 t, %1; cvt.u32.u64 %0, t; }"
        : "=r"(a) : "l"(p));
    return a;
}

#define CP_ASYNC16(sa, gp) \
    asm volatile("cp.async.cg.shared.global [%0], [%1], 16;" :: "r"(sa), "l"(gp))
#define CP_COMMIT() asm volatile("cp.async.commit_group;" ::: "memory")
#define CP_WAIT1()  asm volatile("cp.async.wait_group 1;" ::: "memory")

// Smem: K-slab = 64 halves (128B) per row + 16B pad -> 144B row stride.
// Stage = A tile (128 rows) + B tile (256 rows). 3 stages, 1 CTA/SM.
#define ROWB      144
#define A_BYTES   (128 * ROWB)                // 18432
#define B_BYTES   (256 * ROWB)                // 36864
#define STAGE     (A_BYTES + B_BYTES)         // 55296
#define SMEM_BYTES (3 * STAGE)                // 165888

#define WN4 ((NE * FDIM * DIM) / 4)

// ---------------------------------------------------------------------------
// K0: reset (side-stream A head)
// ---------------------------------------------------------------------------
__global__ void reset_kernel() {
    int i = threadIdx.x;
    if (i < NE) { g_cnt[i] = 0; g_probsum[i] = 0.f; g_fraccnt[i] = 0.f; }
}

// ---------------------------------------------------------------------------
// K1a: gate+up weight cvt (main stream)
// ---------------------------------------------------------------------------
__global__ void __launch_bounds__(256) cvt_gu_kernel(const float* __restrict__ gw,
                                                     const float* __restrict__ uw) {
    __half* gwh = g_gwh; __half* uwh = g_uwh;
    int64_t i = (int64_t)blockIdx.x * blockDim.x + threadIdx.x;
    int64_t stride = (int64_t)gridDim.x * blockDim.x;
    const int64_t total = 2LL * WN4;
    for (; i < total; i += stride) {
        const float* src;
        __half* dst;
        int64_t j = i;
        if (j < WN4) { src = gw; dst = gwh; }
        else         { src = uw; dst = uwh; j -= WN4; }
        float4 v = ((const float4*)src)[j];
        __half2 h0 = __floats2half2_rn(v.x, v.y);
        __half2 h1 = __floats2half2_rn(v.z, v.w);
        uint2 u;
        u.x = *(const uint32_t*)&h0;
        u.y = *(const uint32_t*)&h1;
        ((uint2*)dst)[j] = u;
    }
}

// ---------------------------------------------------------------------------
// K1b: down weight cvt (side-stream B; overlaps gateup)
// ---------------------------------------------------------------------------
__global__ void __launch_bounds__(256) cvt_dw_kernel(const float* __restrict__ dw) {
    __half* dwh = g_dwh;
    int64_t i = (int64_t)blockIdx.x * blockDim.x + threadIdx.x;
    int64_t stride = (int64_t)gridDim.x * blockDim.x;
    for (; i < WN4; i += stride) {
        float4 v = ((const float4*)dw)[i];
        __half2 h0 = __floats2half2_rn(v.x, v.y);
        __half2 h1 = __floats2half2_rn(v.z, v.w);
        uint2 u;
        u.x = *(const uint32_t*)&h0;
        u.y = *(const uint32_t*)&h1;
        ((uint2*)dwh)[i] = u;
    }
}

// ---------------------------------------------------------------------------
// K2: router — 1 warp/token (fp32, exact); also emits fp16 x row.
// ---------------------------------------------------------------------------
__global__ void __launch_bounds__(256) router_kernel(const float* __restrict__ x,
                                                     const float* __restrict__ rw) {
    __shared__ float s_prob[NE], s_frac[NE];
    int tid = threadIdx.x;
    if (tid < NE) { s_prob[tid] = 0.f; s_frac[tid] = 0.f; }
    __syncthreads();

    int lane = tid & 31;
    int tok  = blockIdx.x * 8 + (tid >> 5);

    float acc[NE];
#pragma unroll
    for (int e = 0; e < NE; e++) acc[e] = 0.f;

    const float* xr = x + (size_t)tok * DIM;
    __half* xh = g_xh + (size_t)tok * DIM;
    for (int d = lane; d < DIM; d += 32) {
        float xv = xr[d];
        xh[d] = __float2half_rn(xv);
#pragma unroll
        for (int e = 0; e < NE; e++) acc[e] += xv * rw[e * DIM + d];
    }
#pragma unroll
    for (int e = 0; e < NE; e++) {
#pragma unroll
        for (int o = 16; o > 0; o >>= 1)
            acc[e] += __shfl_xor_sync(0xffffffffu, acc[e], o);
    }

    if (lane == 0) {
        float mx = acc[0];
#pragma unroll
        for (int e = 1; e < NE; e++) mx = fmaxf(mx, acc[e]);
        float p[NE]; float s = 0.f;
#pragma unroll
        for (int e = 0; e < NE; e++) { p[e] = expf(acc[e] - mx); s += p[e]; }
        float inv = 1.f / s;
#pragma unroll
        for (int e = 0; e < NE; e++) p[e] *= inv;

        int e1 = 0;
#pragma unroll
        for (int e = 1; e < NE; e++) if (p[e] > p[e1]) e1 = e;
        int e2 = (e1 == 0) ? 1 : 0;
#pragma unroll
        for (int e = 0; e < NE; e++) if (e != e1 && p[e] > p[e2]) e2 = e;

        float wn = 1.f / (p[e1] + p[e2]);
        g_tok_eid[tok * 2]     = e1;
        g_tok_eid[tok * 2 + 1] = e2;
        g_tok_w[tok * 2]       = p[e1] * wn;
        g_tok_w[tok * 2 + 1]   = p[e2] * wn;
        atomicAdd(&g_cnt[e1], 1);
        atomicAdd(&g_cnt[e2], 1);
#pragma unroll
        for (int e = 0; e < NE; e++) atomicAdd(&s_prob[e], p[e]);
        atomicAdd(&s_frac[e1], 1.f);
        atomicAdd(&s_frac[e2], 1.f);
    }
    __syncthreads();
    if (tid < NE) {
        atomicAdd(&g_probsum[tid], s_prob[tid]);
        atomicAdd(&g_fraccnt[tid], s_frac[tid]);
    }
}

// ---------------------------------------------------------------------------
// K3: scan + fill in one single-block kernel (smem atomics)
// ---------------------------------------------------------------------------
__global__ void __launch_bounds__(256) scanfill_kernel() {
    __shared__ int scur[NE];
    int tid = threadIdx.x;
    if (tid == 0) {
        int off = 0;
        for (int e = 0; e < NE; e++) {
            g_off[e] = off;
            scur[e] = off;
            off += g_cnt[e];
        }
    }
    __syncthreads();
    for (int i = tid; i < NASSIGN; i += 256) {
        int e = g_tok_eid[i];
        int slot = atomicAdd(&scur[e], 1);
        g_slot_token[slot] = i >> 1;
        g_assign_slot[i]   = slot;
    }
}

// ---------------------------------------------------------------------------
// K4: fused gate/up fp16 GEMM, 64x64 warp tiles (128 B smem per mma).
//   CTA 128m x (128 gate | 128 up), 8 warps = 2m x 4n.
//   3-stage cp.async, one barrier per slab, 1 CTA/SM.  (R12, unchanged)
// ---------------------------------------------------------------------------
__global__ void __launch_bounds__(256, 1) gateup_kernel() {
    extern __shared__ __half sm[];
    const int ITERS = DIM / 64;   // 32

    int e   = blockIdx.z;
    int cnt = g_cnt[e];
    int m0  = blockIdx.x * 128;
    if (m0 >= cnt) return;
    int n0  = blockIdx.y * 128;
    int off = g_off[e];

    int tid  = threadIdx.x;
    int lane = tid & 31;
    int w    = tid >> 5;
    int wm   = w & 1;
    int wn   = w >> 1;
    int gid  = lane >> 2;
    int tig  = lane & 3;

    int lrow = tid >> 1;

    int sidx = off + m0 + lrow;
    if (sidx > NASSIGN - 1) sidx = NASSIGN - 1;
    const __half* ga = g_xh + (size_t)g_slot_token[sidx] * DIM + (tid & 1) * 32;
    const __half* gg = g_gwh + ((size_t)e * FDIM + n0 + lrow) * DIM + (tid & 1) * 32;
    const __half* gu = g_uwh + ((size_t)e * FDIM + n0 + lrow) * DIM + (tid & 1) * 32;

    uint32_t sb = smem_u32(sm);
    uint32_t sa_base  = sb + (uint32_t)(lrow * ROWB + (tid & 1) * 64);
    uint32_t sbg_base = sa_base + A_BYTES;
    uint32_t sbu_base = sbg_base + 128 * ROWB;
    int wstage = 0;

    auto issue = [&]() {
        uint32_t st = (uint32_t)(wstage * STAGE);
#pragma unroll
        for (int j = 0; j < 4; j++) CP_ASYNC16(sa_base + st + j * 16, ga + j * 8);
#pragma unroll
        for (int j = 0; j < 4; j++) CP_ASYNC16(sbg_base + st + j * 16, gg + j * 8);
#pragma unroll
        for (int j = 0; j < 4; j++) CP_ASYNC16(sbu_base + st + j * 16, gu + j * 8);
        CP_COMMIT();
        ga += 64; gg += 64; gu += 64;
        wstage = (wstage == 2) ? 0 : wstage + 1;
    };

    int lane15 = lane & 15;
    uint32_t colb = (uint32_t)((lane >> 4) * 16);
    uint32_t a_ld = sb + (uint32_t)((wm * 64 + lane15) * ROWB) + colb;
    uint32_t b_ld = sb + A_BYTES + (uint32_t)((wn * 32 + lane15) * ROWB) + colb;

    float cg[4][4][4], cu[4][4][4];
#pragma unroll
    for (int mi = 0; mi < 4; mi++)
#pragma unroll
        for (int ni = 0; ni < 4; ni++)
#pragma unroll
            for (int q = 0; q < 4; q++) { cg[mi][ni][q] = 0.f; cu[mi][ni][q] = 0.f; }

    issue();
    issue();

    int rstage = 0;
#pragma unroll 1
    for (int i = 0; i < ITERS; i++) {
        CP_WAIT1();
        __syncthreads();
        if (i + 2 < ITERS) issue(); else CP_COMMIT();

        uint32_t aS = a_ld + (uint32_t)(rstage * STAGE);
        uint32_t bS = b_ld + (uint32_t)(rstage * STAGE);
        rstage = (rstage == 2) ? 0 : rstage + 1;
#pragma unroll
        for (int kk = 0; kk < 64; kk += 16) {
            uint32_t a[4][4];
#pragma unroll
            for (int mi = 0; mi < 4; mi++)
                LDSM_X4(a[mi][0], a[mi][1], a[mi][2], a[mi][3],
                        aS + kk * 2 + mi * 16 * ROWB);

            uint32_t f0, f1, f2, f3;
#pragma unroll
            for (int q = 0; q < 2; q++) {     // gate halves
                LDSM_X4(f0, f1, f2, f3, bS + kk * 2 + q * 16 * ROWB);
#pragma unroll
                for (int mi = 0; mi < 4; mi++) {
                    mma_f16(cg[mi][q * 2],     a[mi], f0, f2);
                    mma_f16(cg[mi][q * 2 + 1], a[mi], f1, f3);
                }
            }
#pragma unroll
            for (int q = 0; q < 2; q++) {     // up halves (+128 rows)
                LDSM_X4(f0, f1, f2, f3, bS + kk * 2 + (128 + q * 16) * ROWB);
#pragma unroll
                for (int mi = 0; mi < 4; mi++) {
                    mma_f16(cu[mi][q * 2],     a[mi], f0, f2);
                    mma_f16(cu[mi][q * 2 + 1], a[mi], f1, f3);
                }
            }
        }
    }

#pragma unroll
    for (int mi = 0; mi < 4; mi++) {
#pragma unroll
        for (int ni = 0; ni < 4; ni++) {
            int col = n0 + wn * 32 + ni * 8 + 2 * tig;
            int r0  = m0 + wm * 64 + mi * 16 + gid;
            if (r0 < cnt) {
                __half2 h = __floats2half2_rn(silu(cg[mi][ni][0]) * cu[mi][ni][0],
                                              silu(cg[mi][ni][1]) * cu[mi][ni][1]);
                *(__half2*)&g_hh[(size_t)(off + r0) * FDIM + col] = h;
            }
            if (r0 + 8 < cnt) {
                __half2 h = __floats2half2_rn(silu(cg[mi][ni][2]) * cu[mi][ni][2],
                                              silu(cg[mi][ni][3]) * cu[mi][ni][3]);
                *(__half2*)&g_hh[(size_t)(off + r0 + 8) * FDIM + col] = h;
            }
        }
    }
}

// ---------------------------------------------------------------------------
// K5: down fp16 GEMM (f32 accum), 64x64 warp tiles.  (R12, unchanged)
// ---------------------------------------------------------------------------
__global__ void __launch_bounds__(256, 1) down_kernel() {
    extern __shared__ __half sm[];
    const int ITERS = FDIM / 64;  // 88

    int e   = blockIdx.z;
    int cnt = g_cnt[e];
    int m0  = blockIdx.x * 128;
    if (m0 >= cnt) return;
    int n0  = blockIdx.y * 256;
    int off = g_off[e];

    int tid  = threadIdx.x;
    int lane = tid & 31;
    int w    = tid >> 5;
    int wm   = w & 1;
    int wn   = w >> 1;
    int gid  = lane >> 2;
    int tig  = lane & 3;

    int lrow = tid >> 1;

    int sidx = off + m0 + lrow;
    if (sidx > NASSIGN - 1) sidx = NASSIGN - 1;
    const __half* ga  = g_hh + (size_t)sidx * FDIM + (tid & 1) * 32;
    const __half* gb0 = g_dwh + ((size_t)e * DIM + n0 + lrow) * FDIM + (tid & 1) * 32;
    const __half* gb1 = gb0 + (size_t)128 * FDIM;

    uint32_t sb = smem_u32(sm);
    uint32_t sa_base  = sb + (uint32_t)(lrow * ROWB + (tid & 1) * 64);
    uint32_t sb0_base = sa_base + A_BYTES;
    uint32_t sb1_base = sb0_base + 128 * ROWB;
    int wstage = 0;

    auto issue = [&]() {
        uint32_t st = (uint32_t)(wstage * STAGE);
#pragma unroll
        for (int j = 0; j < 4; j++) CP_ASYNC16(sa_base + st + j * 16, ga + j * 8);
#pragma unroll
        for (int j = 0; j < 4; j++) CP_ASYNC16(sb0_base + st + j * 16, gb0 + j * 8);
#pragma unroll
        for (int j = 0; j < 4; j++) CP_ASYNC16(sb1_base + st + j * 16, gb1 + j * 8);
        CP_COMMIT();
        ga += 64; gb0 += 64; gb1 += 64;
        wstage = (wstage == 2) ? 0 : wstage + 1;
    };

    int lane15 = lane & 15;
    uint32_t colb = (uint32_t)((lane >> 4) * 16);
    uint32_t a_ld = sb + (uint32_t)((wm * 64 + lane15) * ROWB) + colb;
    uint32_t b_ld = sb + A_BYTES + (uint32_t)((wn * 64 + lane15) * ROWB) + colb;

    float c[4][8][4];
#pragma unroll
    for (int mi = 0; mi < 4; mi++)
#pragma unroll
        for (int ni = 0; ni < 8; ni++)
#pragma unroll
            for (int q = 0; q < 4; q++) c[mi][ni][q] = 0.f;

    issue();
    issue();

    int rstage = 0;
#pragma unroll 1
    for (int i = 0; i < ITERS; i++) {
        CP_WAIT1();
        __syncthreads();
        if (i + 2 < ITERS) issue(); else CP_COMMIT();

        uint32_t aS = a_ld + (uint32_t)(rstage * STAGE);
        uint32_t bS = b_ld + (uint32_t)(rstage * STAGE);
        rstage = (rstage == 2) ? 0 : rstage + 1;
#pragma unroll
        for (int kk = 0; kk < 64; kk += 16) {
            uint32_t a[4][4];
#pragma unroll
            for (int mi = 0; mi < 4; mi++)
                LDSM_X4(a[mi][0], a[mi][1], a[mi][2], a[mi][3],
                        aS + kk * 2 + mi * 16 * ROWB);

#pragma unroll
            for (int q = 0; q < 4; q++) {
                uint32_t f0, f1, f2, f3;
                LDSM_X4(f0, f1, f2, f3, bS + kk * 2 + q * 16 * ROWB);
#pragma unroll
                for (int mi = 0; mi < 4; mi++) {
                    mma_f16(c[mi][q * 2],     a[mi], f0, f2);
                    mma_f16(c[mi][q * 2 + 1], a[mi], f1, f3);
                }
            }
        }
    }

#pragma unroll
    for (int mi = 0; mi < 4; mi++) {
#pragma unroll
        for (int ni = 0; ni < 8; ni++) {
            int col = n0 + wn * 64 + ni * 8 + 2 * tig;
            int r0  = m0 + wm * 64 + mi * 16 + gid;
            if (r0 < cnt)
                *(float2*)&g_tmp[(size_t)(off + r0) * DIM + col] =
                    make_float2(c[mi][ni][0], c[mi][ni][1]);
            if (r0 + 8 < cnt)
                *(float2*)&g_tmp[(size_t)(off + r0 + 8) * DIM + col] =
                    make_float2(c[mi][ni][2], c[mi][ni][3]);
        }
    }
}

// ---------------------------------------------------------------------------
// K6: combine — out[t] = w0*tmp[slot0] + w1*tmp[slot1]
// ---------------------------------------------------------------------------
__global__ void __launch_bounds__(256) combine_kernel(float* __restrict__ out) {
    int t = blockIdx.x;
    int d = blockIdx.y * 1024 + threadIdx.x * 4;
    int s0 = g_assign_slot[2 * t];
    int s1 = g_assign_slot[2 * t + 1];
    float w0 = g_tok_w[2 * t];
    float w1 = g_tok_w[2 * t + 1];
    float4 a = *(const float4*)(g_tmp + (size_t)s0 * DIM + d);
    float4 b = *(const float4*)(g_tmp + (size_t)s1 * DIM + d);
    float4 o;
    o.x = w0 * a.x + w1 * b.x;
    o.y = w0 * a.y + w1 * b.y;
    o.z = w0 * a.z + w1 * b.z;
    o.w = w0 * a.w + w1 * b.w;
    *(float4*)(out + (size_t)t * DIM + d) = o;
}

// ---------------------------------------------------------------------------
// K7: aux loss scalar
// ---------------------------------------------------------------------------
__global__ void aux_kernel(float* o) {
    float a = 0.f;
    for (int e = 0; e < NE; e++)
        a += (g_probsum[e] / (float)NTOK) * (g_fraccnt[e] / (float)NTOK);
    *o = (float)NE * a;
}

// ---------------------------------------------------------------------------
// Entry — fork/join two side streams so router-chain and down_w-cvt
// overlap with main-stream work. Handles created once; every call issues
// the identical launch DAG (deterministic work).
// ---------------------------------------------------------------------------
extern "C" void kernel_launch(void* const* d_in, const int* in_sizes, int n_in,
                              void* d_out, int out_size) {
    const float* x  = (const float*)d_in[0];   // [B,T,D]
    const float* rw = (const float*)d_in[1];   // [E,D]
    const float* gw = (const float*)d_in[2];   // [E,F,D]
    const float* uw = (const float*)d_in[3];   // [E,F,D]
    const float* dw = (const float*)d_in[4];   // [E,D,F]
    float* out = (float*)d_out;

    static cudaStream_t sA = nullptr, sB = nullptr;
    static cudaEvent_t evRoot = nullptr, evA = nullptr, evB = nullptr;
    if (sA == nullptr) {
        cudaStreamCreateWithFlags(&sA, cudaStreamNonBlocking);
        cudaStreamCreateWithFlags(&sB, cudaStreamNonBlocking);
        cudaEventCreateWithFlags(&evRoot, cudaEventDisableTiming);
        cudaEventCreateWithFlags(&evA, cudaEventDisableTiming);
        cudaEventCreateWithFlags(&evB, cudaEventDisableTiming);
        cudaFuncSetAttribute(gateup_kernel,
                             cudaFuncAttributeMaxDynamicSharedMemorySize, SMEM_BYTES);
        cudaFuncSetAttribute(down_kernel,
                             cudaFuncAttributeMaxDynamicSharedMemorySize, SMEM_BYTES);
    }

    // Fork
    cudaEventRecord(evRoot, 0);
    cudaStreamWaitEvent(sA, evRoot, 0);
    cudaStreamWaitEvent(sB, evRoot, 0);

    // Side A: routing chain (reset -> router(+x cvt) -> scanfill)
    reset_kernel<<<1, 32, 0, sA>>>();
    router_kernel<<<NTOK / 8, 256, 0, sA>>>(x, rw);
    scanfill_kernel<<<1, 256, 0, sA>>>();
    cudaEventRecord(evA, sA);

    // Side B: down_w conversion (overlaps gateup)
    cvt_dw_kernel<<<2048, 256, 0, sB>>>(dw);
    cudaEventRecord(evB, sB);

    // Main: gate/up conversion, then GEMMs
    cvt_gu_kernel<<<4096, 256>>>(gw, uw);
    cudaStreamWaitEvent(0, evA, 0);
    gateup_kernel<<<dim3(64, FDIM / 128, NE), 256, SMEM_BYTES>>>();
    cudaStreamWaitEvent(0, evB, 0);
    down_kernel<<<dim3(64, DIM / 256, NE), 256, SMEM_BYTES>>>();
    combine_kernel<<<dim3(NTOK, 2), 256>>>(out);
    if (out_size > NTOK * DIM)
        aux_kernel<<<1, 1>>>(out + (size_t)NTOK * DIM);
}